// round 12
// baseline (speedup 1.0000x reference)
#include <cuda_runtime.h>
#include <cuda_bf16.h>

#define Nn 20000
#define Ee 320000
#define EP (Ee + Nn)      // edges + self loops = 340000
#define Bb 128
#define CAT 576

// ---------------- scratch (static __device__, no allocation) ----------------
__device__ float g_H [Nn * 64];       // encoder out (fp32, for head gather)
__device__ float g_XLR[Nn * 512];     // fused conv GEMM out: [xl | xr] per node
__device__ float g_C1[Nn * 256];      // conv1 out (relu)
__device__ float g_C2[Nn * 256];      // conv2 out (relu)
__device__ int   g_deg[Nn];
__device__ int   g_rowptr[Nn + 1];
__device__ int   g_cursor[Nn];
__device__ int   g_col[EP];
__device__ float g_biascat1[512];
__device__ float g_biascat2[512];
// bf16 hi/lo split activation buffers (ping-pong)
__device__ __align__(16) __nv_bfloat16 g_A1H[Nn * 512], g_A1L[Nn * 512];
__device__ __align__(16) __nv_bfloat16 g_A2H[Nn * 512], g_A2L[Nn * 512];
// transposed + bf16-split weights, all six matrices packed:
// enc1 @0 (32768), enc2 @32768 (32768), wl1 @65536 (16384), wr1 @81920 (16384),
// wl2 @98304 (65536), wr2 @163840 (65536) -> total 229376
#define WT_TOTAL 229376
__device__ __align__(16) __nv_bfloat16 g_WT_hi[WT_TOTAL], g_WT_lo[WT_TOTAL];

// ---------------- helpers ----------------------------------------------------
__device__ __forceinline__ void mma_bf16(float c[4],
                                         const unsigned a[4], const unsigned b[2]) {
    asm volatile(
        "mma.sync.aligned.m16n8k16.row.col.f32.bf16.bf16.f32 "
        "{%0,%1,%2,%3}, {%4,%5,%6,%7}, {%8,%9}, {%0,%1,%2,%3};\n"
        : "+f"(c[0]), "+f"(c[1]), "+f"(c[2]), "+f"(c[3])
        : "r"(a[0]), "r"(a[1]), "r"(a[2]), "r"(a[3]),
          "r"(b[0]), "r"(b[1]));
}

__device__ __forceinline__ void ldsm_x4(unsigned r[4], unsigned saddr) {
    asm volatile("ldmatrix.sync.aligned.m8n8.x4.shared.b16 {%0,%1,%2,%3}, [%4];"
        : "=r"(r[0]), "=r"(r[1]), "=r"(r[2]), "=r"(r[3]) : "r"(saddr));
}

__device__ __forceinline__ __nv_bfloat162 split_pair(float x, float y,
                                                     __nv_bfloat162& lo) {
    __nv_bfloat16 hx = __float2bfloat16(x), hy = __float2bfloat16(y);
    lo = __nv_bfloat162(__float2bfloat16(x - __bfloat162float(hx)),
                        __float2bfloat16(y - __bfloat162float(hy)));
    return __nv_bfloat162(hx, hy);
}

// ---------------- fused weight prep (all transposes + bias concats) ----------
__global__ void prep_weights_kernel(
    const float* __restrict__ ew1, const float* __restrict__ ew2,
    const float* __restrict__ wl1, const float* __restrict__ wr1,
    const float* __restrict__ wl2, const float* __restrict__ wr2,
    const float* __restrict__ bl1, const float* __restrict__ br1,
    const float* __restrict__ bl2, const float* __restrict__ br2)
{
    int i = blockIdx.x * blockDim.x + threadIdx.x;
    if (i < WT_TOTAL) {
        const float* W; int K, N, j = i;
        if (j < 32768)       { W = ew1; K = 64;  N = 512; }
        else if (j < 65536)  { W = ew2; K = 512; N = 64;  j -= 32768; }
        else if (j < 81920)  { W = wl1; K = 64;  N = 256; j -= 65536; }
        else if (j < 98304)  { W = wr1; K = 64;  N = 256; j -= 81920; }
        else if (j < 163840) { W = wl2; K = 256; N = 256; j -= 98304; }
        else                 { W = wr2; K = 256; N = 256; j -= 163840; }
        int n = j / K, k = j % K;
        float f = W[(size_t)k * N + n];
        __nv_bfloat16 h = __float2bfloat16(f);
        g_WT_hi[i] = h;
        g_WT_lo[i] = __float2bfloat16(f - __bfloat162float(h));
    } else if (i < WT_TOTAL + 512) {
        int t = i - WT_TOTAL;
        g_biascat1[t] = (t < 256) ? bl1[t] : br1[t - 256];
    } else if (i < WT_TOTAL + 1024) {
        int t = i - WT_TOTAL - 512;
        g_biascat2[t] = (t < 256) ? bl2[t] : br2[t - 256];
    }
}

// ---------------- activation split (for the network input x) -----------------
__global__ void split_A_kernel(const float* __restrict__ A,
                               __nv_bfloat16* __restrict__ H,
                               __nv_bfloat16* __restrict__ L, int total4) {
    int i = blockIdx.x * blockDim.x + threadIdx.x;
    if (i >= total4) return;
    float4 v = ((const float4*)A)[i];
    __nv_bfloat162 l0, l1;
    __nv_bfloat162 h0 = split_pair(v.x, v.y, l0);
    __nv_bfloat162 h1 = split_pair(v.z, v.w, l1);
    ((__nv_bfloat162*)H)[2 * i]     = h0;
    ((__nv_bfloat162*)H)[2 * i + 1] = h1;
    ((__nv_bfloat162*)L)[2 * i]     = l0;
    ((__nv_bfloat162*)L)[2 * i + 1] = l1;
}

// ---------------- 3-term bf16 GEMM (R8 config + x4 B loads) -------------------
// C[M,N] = act(A @ W + bias); A presplit [M,K] bf16 hi/lo; W presplit [N,K].
// 256 threads, block tile 128(m) x 64(n), k-chunk 32, ldmatrix fragments.
// mode: 0 = fp32 C only; 1 = fp32 C + split to SH/SL; 2 = split only.
__global__ __launch_bounds__(256) void gemm_bf16_ldsm(
    const __nv_bfloat16* __restrict__ AH, const __nv_bfloat16* __restrict__ AL,
    const __nv_bfloat16* __restrict__ WH, const __nv_bfloat16* __restrict__ WL,
    const float* __restrict__ bias, float* __restrict__ C,
    __nv_bfloat16* __restrict__ SH, __nv_bfloat16* __restrict__ SL,
    int M, int N, int K, int mode, int do_relu)
{
    __shared__ __nv_bfloat16 sAH[128][40], sAL[128][40];   // 80B rows
    __shared__ __nv_bfloat16 sBH[64][40],  sBL[64][40];

    const int tid = threadIdx.x;
    const int warp = tid >> 5, lane = tid & 31;
    const int wm = warp & 3, wn = warp >> 2;     // warp tile 32(m) x 32(n)
    const int row0 = blockIdx.y * 128, col0 = blockIdx.x * 64;

    const unsigned baseAH = (unsigned)__cvta_generic_to_shared(&sAH[0][0]);
    const unsigned baseAL = (unsigned)__cvta_generic_to_shared(&sAL[0][0]);
    const unsigned baseBH = (unsigned)__cvta_generic_to_shared(&sBH[0][0]);
    const unsigned baseBL = (unsigned)__cvta_generic_to_shared(&sBL[0][0]);

    const int q  = lane >> 3, r8 = lane & 7;      // A x4 mapping
    const int oc = lane >> 3;                     // octet for B x4 mapping

    float acc[2][4][4];
#pragma unroll
    for (int mt = 0; mt < 2; mt++)
#pragma unroll
        for (int nt = 0; nt < 4; nt++)
#pragma unroll
            for (int i = 0; i < 4; i++) acc[mt][nt][i] = 0.f;

    for (int k0 = 0; k0 < K; k0 += 32) {
#pragma unroll
        for (int i = tid; i < 512; i += 256) {
            int r = i >> 2, qq = i & 3;
            int gr = min(row0 + r, M - 1);
            size_t go = (size_t)gr * K + k0 + qq * 8;
            *(uint4*)&sAH[r][qq * 8] = *(const uint4*)(AH + go);
            *(uint4*)&sAL[r][qq * 8] = *(const uint4*)(AL + go);
        }
        {
            int r = tid >> 2, qq = tid & 3;
            size_t go = (size_t)(col0 + r) * K + k0 + qq * 8;
            *(uint4*)&sBH[r][qq * 8] = *(const uint4*)(WH + go);
            *(uint4*)&sBL[r][qq * 8] = *(const uint4*)(WL + go);
        }
        __syncthreads();

#pragma unroll
        for (int s = 0; s < 2; s++) {
            const int ka = s * 16 + (q >> 1) * 8;
            unsigned ahi[2][4], alo[2][4];
#pragma unroll
            for (int mt = 0; mt < 2; mt++) {
                int m = wm * 32 + mt * 16 + r8 + (q & 1) * 8;
                unsigned off = (unsigned)(m * 40 + ka) * 2;
                ldsm_x4(ahi[mt], baseAH + off);
                ldsm_x4(alo[mt], baseAL + off);
            }
            // B fragments: x4 loads two n8-tiles (nt pair) with both k8 halves.
            // octet 0: (nt0, kb0) 1: (nt0, kb8) 2: (nt0+1, kb0) 3: (nt0+1, kb8)
            unsigned bhi[2][4], blo[2][4];
#pragma unroll
            for (int ntp = 0; ntp < 2; ntp++) {
                int n = wn * 32 + (ntp * 2 + (oc >> 1)) * 8 + r8;
                int kb = s * 16 + (oc & 1) * 8;
                unsigned off = (unsigned)(n * 40 + kb) * 2;
                ldsm_x4(bhi[ntp], baseBH + off);
                ldsm_x4(blo[ntp], baseBL + off);
            }
#pragma unroll
            for (int nt = 0; nt < 4; nt++) {
                const unsigned* bh = &bhi[nt >> 1][(nt & 1) * 2];
                const unsigned* bl = &blo[nt >> 1][(nt & 1) * 2];
#pragma unroll
                for (int mt = 0; mt < 2; mt++) {
                    mma_bf16(acc[mt][nt], ahi[mt], bl);
                    mma_bf16(acc[mt][nt], alo[mt], bh);
                    mma_bf16(acc[mt][nt], ahi[mt], bh);
                }
            }
        }
        __syncthreads();
    }

    const int lr = lane >> 2, lc = lane & 3;
#pragma unroll
    for (int mt = 0; mt < 2; mt++) {
#pragma unroll
        for (int nt = 0; nt < 4; nt++) {
            int r = row0 + wm * 32 + mt * 16 + lr;
            int n = col0 + wn * 32 + nt * 8 + 2 * lc;
            float b0 = bias[n], b1 = bias[n + 1];
            float v0 = acc[mt][nt][0] + b0, v1 = acc[mt][nt][1] + b1;
            float v2 = acc[mt][nt][2] + b0, v3 = acc[mt][nt][3] + b1;
            if (do_relu) {
                v0 = fmaxf(v0, 0.f); v1 = fmaxf(v1, 0.f);
                v2 = fmaxf(v2, 0.f); v3 = fmaxf(v3, 0.f);
            }
#pragma unroll
            for (int h = 0; h < 2; h++) {
                int rr = r + h * 8;
                if (rr >= M) continue;
                float e0 = h ? v2 : v0, e1 = h ? v3 : v1;
                if (mode != 2)
                    *(float2*)(C + (size_t)rr * N + n) = make_float2(e0, e1);
                if (mode >= 1) {
                    __nv_bfloat162 lo;
                    __nv_bfloat162 hi = split_pair(e0, e1, lo);
                    *(__nv_bfloat162*)(SH + (size_t)rr * N + n) = hi;
                    *(__nv_bfloat162*)(SL + (size_t)rr * N + n) = lo;
                }
            }
        }
    }
}

// ---------------- CSR build ----------------
__global__ void zero_deg_kernel() {
    int i = blockIdx.x * blockDim.x + threadIdx.x;
    if (i < Nn) g_deg[i] = 0;
}

__global__ void count_kernel(const int* __restrict__ ei) {
    int e = blockIdx.x * blockDim.x + threadIdx.x;
    if (e >= EP) return;
    int d = (e < Ee) ? ei[Ee + e] : (e - Ee);
    atomicAdd(&g_deg[d], 1);
}

__global__ __launch_bounds__(1024) void scan_kernel() {
    __shared__ int s[1024];
    int tid = threadIdx.x;
    const int chunk = (Nn + 1023) / 1024;
    int start = tid * chunk;
    int sum = 0;
    for (int i = 0; i < chunk; i++) {
        int idx = start + i;
        if (idx < Nn) sum += g_deg[idx];
    }
    s[tid] = sum;
    __syncthreads();
    for (int off = 1; off < 1024; off <<= 1) {
        int v = (tid >= off) ? s[tid - off] : 0;
        __syncthreads();
        s[tid] += v;
        __syncthreads();
    }
    int run = (tid > 0) ? s[tid - 1] : 0;
    for (int i = 0; i < chunk; i++) {
        int idx = start + i;
        if (idx < Nn) { g_rowptr[idx] = run; g_cursor[idx] = run; run += g_deg[idx]; }
    }
    if (tid == 1023) g_rowptr[Nn] = s[1023];
}

__global__ void scatter_kernel(const int* __restrict__ ei) {
    int e = blockIdx.x * blockDim.x + threadIdx.x;
    if (e >= EP) return;
    int s, d;
    if (e < Ee) { s = ei[e]; d = ei[Ee + e]; }
    else        { s = e - Ee; d = s; }
    int pos = atomicAdd(&g_cursor[d], 1);
    g_col[pos] = s;
}

// ------- GATv2 aggregation: one warp per dst node, online softmax, 4-edge unroll
__device__ __forceinline__ float lrelu(float v) { return v > 0.f ? v : 0.2f * v; }

__device__ __forceinline__ float edge_score(const float4& a, const float4& b,
                                            const float4& xr0, const float4& xr1,
                                            const float4& at0, const float4& at1) {
    float p = 0.f;
    p = fmaf(at0.x, lrelu(a.x + xr0.x), p);
    p = fmaf(at0.y, lrelu(a.y + xr0.y), p);
    p = fmaf(at0.z, lrelu(a.z + xr0.z), p);
    p = fmaf(at0.w, lrelu(a.w + xr0.w), p);
    p = fmaf(at1.x, lrelu(b.x + xr1.x), p);
    p = fmaf(at1.y, lrelu(b.y + xr1.y), p);
    p = fmaf(at1.z, lrelu(b.z + xr1.z), p);
    p = fmaf(at1.w, lrelu(b.w + xr1.w), p);
    p += __shfl_xor_sync(0xffffffffu, p, 1);
    p += __shfl_xor_sync(0xffffffffu, p, 2);
    p += __shfl_xor_sync(0xffffffffu, p, 4);
    return p;
}

__global__ __launch_bounds__(256) void gat_agg_kernel(
    const float* __restrict__ XLR,
    const float* __restrict__ att, const float* __restrict__ bias,
    float* __restrict__ OUT,
    __nv_bfloat16* __restrict__ SH, __nv_bfloat16* __restrict__ SL)
{
    int warp = (blockIdx.x * blockDim.x + threadIdx.x) >> 5;
    if (warp >= Nn) return;
    int lane = threadIdx.x & 31;

    const float4* xr4 = reinterpret_cast<const float4*>(XLR + (size_t)warp * 512 + 256 + lane * 8);
    float4 xr0 = xr4[0], xr1 = xr4[1];
    const float4* at4 = reinterpret_cast<const float4*>(att + lane * 8);
    float4 at0 = at4[0], at1 = at4[1];

    int s0 = g_rowptr[warp], s1 = g_rowptr[warp + 1];

    float m = -3.0e38f, denom = 0.f;
    float acc[8] = {0.f, 0.f, 0.f, 0.f, 0.f, 0.f, 0.f, 0.f};

    int slot = s0;
    for (; slot + 4 <= s1; slot += 4) {
        int src0 = g_col[slot],     src1 = g_col[slot + 1];
        int src2 = g_col[slot + 2], src3 = g_col[slot + 3];
        const float4* x0 = reinterpret_cast<const float4*>(XLR + (size_t)src0 * 512 + lane * 8);
        const float4* x1 = reinterpret_cast<const float4*>(XLR + (size_t)src1 * 512 + lane * 8);
        const float4* x2 = reinterpret_cast<const float4*>(XLR + (size_t)src2 * 512 + lane * 8);
        const float4* x3 = reinterpret_cast<const float4*>(XLR + (size_t)src3 * 512 + lane * 8);
        float4 a0 = x0[0], b0 = x0[1];
        float4 a1 = x1[0], b1 = x1[1];
        float4 a2 = x2[0], b2 = x2[1];
        float4 a3 = x3[0], b3 = x3[1];

        float p0 = edge_score(a0, b0, xr0, xr1, at0, at1);
        float p1 = edge_score(a1, b1, xr0, xr1, at0, at1);
        float p2 = edge_score(a2, b2, xr0, xr1, at0, at1);
        float p3 = edge_score(a3, b3, xr0, xr1, at0, at1);

        float mnew = fmaxf(fmaxf(m, fmaxf(p0, p1)), fmaxf(p2, p3));
        float sc = __expf(m - mnew);
        float e0 = __expf(p0 - mnew);
        float e1 = __expf(p1 - mnew);
        float e2 = __expf(p2 - mnew);
        float e3 = __expf(p3 - mnew);
        m = mnew;
        denom = denom * sc + e0 + e1 + e2 + e3;
        acc[0] = fmaf(e3, a3.x, fmaf(e2, a2.x, fmaf(e1, a1.x, fmaf(e0, a0.x, acc[0] * sc))));
        acc[1] = fmaf(e3, a3.y, fmaf(e2, a2.y, fmaf(e1, a1.y, fmaf(e0, a0.y, acc[1] * sc))));
        acc[2] = fmaf(e3, a3.z, fmaf(e2, a2.z, fmaf(e1, a1.z, fmaf(e0, a0.z, acc[2] * sc))));
        acc[3] = fmaf(e3, a3.w, fmaf(e2, a2.w, fmaf(e1, a1.w, fmaf(e0, a0.w, acc[3] * sc))));
        acc[4] = fmaf(e3, b3.x, fmaf(e2, b2.x, fmaf(e1, b1.x, fmaf(e0, b0.x, acc[4] * sc))));
        acc[5] = fmaf(e3, b3.y, fmaf(e2, b2.y, fmaf(e1, b1.y, fmaf(e0, b0.y, acc[5] * sc))));
        acc[6] = fmaf(e3, b3.z, fmaf(e2, b2.z, fmaf(e1, b1.z, fmaf(e0, b0.z, acc[6] * sc))));
        acc[7] = fmaf(e3, b3.w, fmaf(e2, b2.w, fmaf(e1, b1.w, fmaf(e0, b0.w, acc[7] * sc))));
    }
    for (; slot < s1; slot++) {
        int src = g_col[slot];
        const float4* x0 = reinterpret_cast<const float4*>(XLR + (size_t)src * 512 + lane * 8);
        float4 a = x0[0], b = x0[1];
        float p = edge_score(a, b, xr0, xr1, at0, at1);
        float mnew = fmaxf(m, p);
        float sc = __expf(m - mnew);
        float ex = __expf(p - mnew);
        m = mnew;
        denom = denom * sc + ex;
        acc[0] = fmaf(ex, a.x, acc[0] * sc);
        acc[1] = fmaf(ex, a.y, acc[1] * sc);
        acc[2] = fmaf(ex, a.z, acc[2] * sc);
        acc[3] = fmaf(ex, a.w, acc[3] * sc);
        acc[4] = fmaf(ex, b.x, acc[4] * sc);
        acc[5] = fmaf(ex, b.y, acc[5] * sc);
        acc[6] = fmaf(ex, b.z, acc[6] * sc);
        acc[7] = fmaf(ex, b.w, acc[7] * sc);
    }

    float inv = 1.0f / (denom + 1e-16f);
    const float4* bi4 = reinterpret_cast<const float4*>(bias + lane * 8);
    float4 bb0 = bi4[0], bb1 = bi4[1];
    float o[8];
    o[0] = fmaxf(acc[0] * inv + bb0.x, 0.f);
    o[1] = fmaxf(acc[1] * inv + bb0.y, 0.f);
    o[2] = fmaxf(acc[2] * inv + bb0.z, 0.f);
    o[3] = fmaxf(acc[3] * inv + bb0.w, 0.f);
    o[4] = fmaxf(acc[4] * inv + bb1.x, 0.f);
    o[5] = fmaxf(acc[5] * inv + bb1.y, 0.f);
    o[6] = fmaxf(acc[6] * inv + bb1.z, 0.f);
    o[7] = fmaxf(acc[7] * inv + bb1.w, 0.f);

    float4* out4 = reinterpret_cast<float4*>(OUT + (size_t)warp * 256 + lane * 8);
    out4[0] = make_float4(o[0], o[1], o[2], o[3]);
    out4[1] = make_float4(o[4], o[5], o[6], o[7]);

    if (SH) {
        size_t base = (size_t)warp * 256 + lane * 8;
#pragma unroll
        for (int j = 0; j < 4; j++) {
            __nv_bfloat162 lo;
            __nv_bfloat162 hi = split_pair(o[2 * j], o[2 * j + 1], lo);
            *(__nv_bfloat162*)(SH + base + 2 * j) = hi;
            *(__nv_bfloat162*)(SL + base + 2 * j) = lo;
        }
    }
}

// ---------------- dueling head (gather fused) ---------------------------------
__global__ __launch_bounds__(128) void duel_kernel(
    const int* __restrict__ indices,
    const float* __restrict__ qw1, const float* __restrict__ qb1,
    const float* __restrict__ qw2, const float* __restrict__ qb2,
    const float* __restrict__ vw1, const float* __restrict__ vb1,
    const float* __restrict__ vw2, const float* __restrict__ vb2,
    float* __restrict__ out)
{
    int b = blockIdx.x;
    int t = threadIdx.x;
    int node = indices[b];
    __shared__ float f[CAT];
    __shared__ float r0[128], r1[128], rv[128];
    for (int i = t; i < CAT; i += 128) {
        float v;
        if (i < 64)       v = g_H [node * 64 + i];
        else if (i < 320) v = g_C1[node * 256 + (i - 64)];
        else              v = g_C2[node * 256 + (i - 320)];
        f[i] = v;
    }
    __syncthreads();

    float sq = qb1[t], sv = vb1[t];
    for (int j = 0; j < CAT; j++) {
        float fv = f[j];
        sq = fmaf(fv, qw1[j * 128 + t], sq);
        sv = fmaf(fv, vw1[j * 128 + t], sv);
    }
    sq = fmaxf(sq, 0.f);
    sv = fmaxf(sv, 0.f);
    r0[t] = sq * qw2[t * 2 + 0];
    r1[t] = sq * qw2[t * 2 + 1];
    rv[t] = sv * vw2[t];
    __syncthreads();
    for (int off = 64; off > 0; off >>= 1) {
        if (t < off) {
            r0[t] += r0[t + off];
            r1[t] += r1[t + off];
            rv[t] += rv[t + off];
        }
        __syncthreads();
    }
    if (t == 0) {
        float q0 = r0[0] + qb2[0];
        float q1 = r1[0] + qb2[1];
        float v  = rv[0] + vb2[0];
        float mth = 0.5f * (q0 + q1);
        out[b * 2 + 0] = q0 - mth + v;
        out[b * 2 + 1] = q1 - mth + v;
    }
}

// ---------------- host ----------------
extern "C" void kernel_launch(void* const* d_in, const int* in_sizes, int n_in,
                              void* d_out, int out_size)
{
    const float* x       = (const float*)d_in[0];
    const int*   ei      = (const int*)  d_in[1];
    const int*   indices = (const int*)  d_in[2];
    const float* enc_w1 = (const float*)d_in[3],  *enc_b1 = (const float*)d_in[4];
    const float* enc_w2 = (const float*)d_in[5],  *enc_b2 = (const float*)d_in[6];
    const float* wl1 = (const float*)d_in[7],  *bl1 = (const float*)d_in[8];
    const float* wr1 = (const float*)d_in[9],  *br1 = (const float*)d_in[10];
    const float* att1 = (const float*)d_in[11], *bias1 = (const float*)d_in[12];
    const float* wl2 = (const float*)d_in[13], *bl2 = (const float*)d_in[14];
    const float* wr2 = (const float*)d_in[15], *br2 = (const float*)d_in[16];
    const float* att2 = (const float*)d_in[17], *bias2 = (const float*)d_in[18];
    const float* qw1 = (const float*)d_in[19], *qb1 = (const float*)d_in[20];
    const float* qw2 = (const float*)d_in[21], *qb2 = (const float*)d_in[22];
    const float* vw1 = (const float*)d_in[23], *vb1 = (const float*)d_in[24];
    const float* vw2 = (const float*)d_in[25], *vb2 = (const float*)d_in[26];

    float *pH, *pXLR, *pC1, *pC2, *pB1, *pB2;
    __nv_bfloat16 *pA1H, *pA1L, *pA2H, *pA2L, *pWH, *pWL;
    cudaGetSymbolAddress((void**)&pH,   g_H);
    cudaGetSymbolAddress((void**)&pXLR, g_XLR);
    cudaGetSymbolAddress((void**)&pC1,  g_C1);
    cudaGetSymbolAddress((void**)&pC2,  g_C2);
    cudaGetSymbolAddress((void**)&pB1,  g_biascat1);
    cudaGetSymbolAddress((void**)&pB2,  g_biascat2);
    cudaGetSymbolAddress((void**)&pA1H, g_A1H);
    cudaGetSymbolAddress((void**)&pA1L, g_A1L);
    cudaGetSymbolAddress((void**)&pA2H, g_A2H);
    cudaGetSymbolAddress((void**)&pA2L, g_A2L);
    cudaGetSymbolAddress((void**)&pWH,  g_WT_hi);
    cudaGetSymbolAddress((void**)&pWL,  g_WT_lo);

    // side stream + events (created once; no device memory)
    static cudaStream_t s_csr = nullptr;
    static cudaEvent_t evFork = nullptr, evJoin = nullptr, evPrep = nullptr;
    if (!s_csr) {
        cudaStreamCreateWithFlags(&s_csr, cudaStreamNonBlocking);
        cudaEventCreateWithFlags(&evFork, cudaEventDisableTiming);
        cudaEventCreateWithFlags(&evJoin, cudaEventDisableTiming);
        cudaEventCreateWithFlags(&evPrep, cudaEventDisableTiming);
    }

    const int MB = (Nn + 127) / 128;   // 157 row-blocks

    // fork: weight prep + CSR chain on side stream; split_A on main
    cudaEventRecord(evFork, 0);
    cudaStreamWaitEvent(s_csr, evFork, 0);

    prep_weights_kernel<<<(WT_TOTAL + 1024 + 255) / 256, 256, 0, s_csr>>>(
        enc_w1, enc_w2, wl1, wr1, wl2, wr2, bl1, br1, bl2, br2);
    cudaEventRecord(evPrep, s_csr);
    zero_deg_kernel<<<(Nn + 255) / 256, 256, 0, s_csr>>>();
    count_kernel<<<(EP + 255) / 256, 256, 0, s_csr>>>(ei);
    scan_kernel<<<1, 1024, 0, s_csr>>>();
    scatter_kernel<<<(EP + 255) / 256, 256, 0, s_csr>>>(ei);
    cudaEventRecord(evJoin, s_csr);

    // main: input split (independent of weights)
    split_A_kernel<<<(Nn * 64 / 4 + 255) / 256, 256>>>(x, pA1H, pA1L, Nn * 64 / 4);

    // enc1 needs split_A (main) + prep (side)
    cudaStreamWaitEvent(0, evPrep, 0);
    gemm_bf16_ldsm<<<dim3(8, MB), 256>>>(pA1H, pA1L, pWH, pWL, enc_b1,
                                         nullptr, pA2H, pA2L, Nn, 512, 64, 2, 1);
    gemm_bf16_ldsm<<<dim3(1, MB), 256>>>(pA2H, pA2L, pWH + 32768, pWL + 32768, enc_b2,
                                         pH, pA1H, pA1L, Nn, 64, 512, 1, 1);
    gemm_bf16_ldsm<<<dim3(8, MB), 256>>>(pA1H, pA1L, pWH + 65536, pWL + 65536, pB1,
                                         pXLR, nullptr, nullptr, Nn, 512, 64, 0, 0);

    // join: agg needs both conv1 (main) and CSR (side)
    cudaStreamWaitEvent(0, evJoin, 0);
    gat_agg_kernel<<<Nn / 8, 256>>>(pXLR, att1, bias1, pC1, pA2H, pA2L);

    gemm_bf16_ldsm<<<dim3(8, MB), 256>>>(pA2H, pA2L, pWH + 98304, pWL + 98304, pB2,
                                         pXLR, nullptr, nullptr, Nn, 512, 256, 0, 0);
    gat_agg_kernel<<<Nn / 8, 256>>>(pXLR, att2, bias2, pC2, nullptr, nullptr);

    duel_kernel<<<Bb, 128>>>(indices, qw1, qb1, qw2, qb2, vw1, vb1, vw2, vb2,
                             (float*)d_out);
}

// round 13
// speedup vs baseline: 1.0929x; 1.0929x over previous
#include <cuda_runtime.h>
#include <cuda_bf16.h>

#define Nn 20000
#define Ee 320000
#define EP (Ee + Nn)      // edges + self loops = 340000
#define Bb 128
#define CAT 576

// ---------------- scratch (static __device__, no allocation) ----------------
__device__ float g_H [Nn * 64];       // encoder out (fp32, for head gather)
__device__ float g_XLR[Nn * 512];     // fused conv GEMM out: [xl | xr] per node
__device__ float g_C1[Nn * 256];      // conv1 out (relu)
__device__ float g_C2[Nn * 256];      // conv2 out (relu)
__device__ int   g_deg[Nn];
__device__ int   g_rowptr[Nn + 1];
__device__ int   g_cursor[Nn];
__device__ int   g_col[EP];
__device__ float g_biascat1[512];
__device__ float g_biascat2[512];
// bf16 hi/lo split activation buffers (ping-pong)
__device__ __align__(16) __nv_bfloat16 g_A1H[Nn * 512], g_A1L[Nn * 512];
__device__ __align__(16) __nv_bfloat16 g_A2H[Nn * 512], g_A2L[Nn * 512];
// transposed + bf16-split weights, all six matrices packed:
// enc1 @0 (32768), enc2 @32768 (32768), wl1 @65536 (16384), wr1 @81920 (16384),
// wl2 @98304 (65536), wr2 @163840 (65536) -> total 229376
#define WT_TOTAL 229376
__device__ __align__(16) __nv_bfloat16 g_WT_hi[WT_TOTAL], g_WT_lo[WT_TOTAL];

// ---------------- helpers ----------------------------------------------------
__device__ __forceinline__ void mma_bf16(float c[4],
                                         const unsigned a[4], const unsigned b[2]) {
    asm volatile(
        "mma.sync.aligned.m16n8k16.row.col.f32.bf16.bf16.f32 "
        "{%0,%1,%2,%3}, {%4,%5,%6,%7}, {%8,%9}, {%0,%1,%2,%3};\n"
        : "+f"(c[0]), "+f"(c[1]), "+f"(c[2]), "+f"(c[3])
        : "r"(a[0]), "r"(a[1]), "r"(a[2]), "r"(a[3]),
          "r"(b[0]), "r"(b[1]));
}

__device__ __forceinline__ void ldsm_x4(unsigned r[4], unsigned saddr) {
    asm volatile("ldmatrix.sync.aligned.m8n8.x4.shared.b16 {%0,%1,%2,%3}, [%4];"
        : "=r"(r[0]), "=r"(r[1]), "=r"(r[2]), "=r"(r[3]) : "r"(saddr));
}
__device__ __forceinline__ void ldsm_x2(unsigned r[2], unsigned saddr) {
    asm volatile("ldmatrix.sync.aligned.m8n8.x2.shared.b16 {%0,%1}, [%2];"
        : "=r"(r[0]), "=r"(r[1]) : "r"(saddr));
}

__device__ __forceinline__ __nv_bfloat162 split_pair(float x, float y,
                                                     __nv_bfloat162& lo) {
    __nv_bfloat16 hx = __float2bfloat16(x), hy = __float2bfloat16(y);
    lo = __nv_bfloat162(__float2bfloat16(x - __bfloat162float(hx)),
                        __float2bfloat16(y - __bfloat162float(hy)));
    return __nv_bfloat162(hx, hy);
}

// ---------------- fused weight prep (all transposes + bias concats) ----------
__global__ void prep_weights_kernel(
    const float* __restrict__ ew1, const float* __restrict__ ew2,
    const float* __restrict__ wl1, const float* __restrict__ wr1,
    const float* __restrict__ wl2, const float* __restrict__ wr2,
    const float* __restrict__ bl1, const float* __restrict__ br1,
    const float* __restrict__ bl2, const float* __restrict__ br2)
{
    int i = blockIdx.x * blockDim.x + threadIdx.x;
    if (i < WT_TOTAL) {
        const float* W; int K, N, j = i;
        if (j < 32768)       { W = ew1; K = 64;  N = 512; }
        else if (j < 65536)  { W = ew2; K = 512; N = 64;  j -= 32768; }
        else if (j < 81920)  { W = wl1; K = 64;  N = 256; j -= 65536; }
        else if (j < 98304)  { W = wr1; K = 64;  N = 256; j -= 81920; }
        else if (j < 163840) { W = wl2; K = 256; N = 256; j -= 98304; }
        else                 { W = wr2; K = 256; N = 256; j -= 163840; }
        int n = j / K, k = j % K;
        float f = W[(size_t)k * N + n];
        __nv_bfloat16 h = __float2bfloat16(f);
        g_WT_hi[i] = h;
        g_WT_lo[i] = __float2bfloat16(f - __bfloat162float(h));
    } else if (i < WT_TOTAL + 512) {
        int t = i - WT_TOTAL;
        g_biascat1[t] = (t < 256) ? bl1[t] : br1[t - 256];
    } else if (i < WT_TOTAL + 1024) {
        int t = i - WT_TOTAL - 512;
        g_biascat2[t] = (t < 256) ? bl2[t] : br2[t - 256];
    }
}

// ---------------- activation split (for the network input x) -----------------
__global__ void split_A_kernel(const float* __restrict__ A,
                               __nv_bfloat16* __restrict__ H,
                               __nv_bfloat16* __restrict__ L, int total4) {
    int i = blockIdx.x * blockDim.x + threadIdx.x;
    if (i >= total4) return;
    float4 v = ((const float4*)A)[i];
    __nv_bfloat162 l0, l1;
    __nv_bfloat162 h0 = split_pair(v.x, v.y, l0);
    __nv_bfloat162 h1 = split_pair(v.z, v.w, l1);
    ((__nv_bfloat162*)H)[2 * i]     = h0;
    ((__nv_bfloat162*)H)[2 * i + 1] = h1;
    ((__nv_bfloat162*)L)[2 * i]     = l0;
    ((__nv_bfloat162*)L)[2 * i + 1] = l1;
}

// ---------------- 3-term bf16 GEMM (R6/R8/R11-proven config) ------------------
// C[M,N] = act(A @ W + bias); A presplit [M,K] bf16 hi/lo; W presplit [N,K].
// 256 threads, block tile 128(m) x 64(n), k-chunk 32, ldmatrix fragments.
// mode: 0 = fp32 C only; 1 = fp32 C + split to SH/SL; 2 = split only.
__global__ __launch_bounds__(256) void gemm_bf16_ldsm(
    const __nv_bfloat16* __restrict__ AH, const __nv_bfloat16* __restrict__ AL,
    const __nv_bfloat16* __restrict__ WH, const __nv_bfloat16* __restrict__ WL,
    const float* __restrict__ bias, float* __restrict__ C,
    __nv_bfloat16* __restrict__ SH, __nv_bfloat16* __restrict__ SL,
    int M, int N, int K, int mode, int do_relu)
{
    __shared__ __nv_bfloat16 sAH[128][40], sAL[128][40];   // 80B rows
    __shared__ __nv_bfloat16 sBH[64][40],  sBL[64][40];

    const int tid = threadIdx.x;
    const int warp = tid >> 5, lane = tid & 31;
    const int wm = warp & 3, wn = warp >> 2;     // warp tile 32(m) x 32(n)
    const int row0 = blockIdx.y * 128, col0 = blockIdx.x * 64;

    const unsigned baseAH = (unsigned)__cvta_generic_to_shared(&sAH[0][0]);
    const unsigned baseAL = (unsigned)__cvta_generic_to_shared(&sAL[0][0]);
    const unsigned baseBH = (unsigned)__cvta_generic_to_shared(&sBH[0][0]);
    const unsigned baseBL = (unsigned)__cvta_generic_to_shared(&sBL[0][0]);

    const int q  = lane >> 3, r8 = lane & 7;
    const int l16 = lane & 15;

    float acc[2][4][4];
#pragma unroll
    for (int mt = 0; mt < 2; mt++)
#pragma unroll
        for (int nt = 0; nt < 4; nt++)
#pragma unroll
            for (int i = 0; i < 4; i++) acc[mt][nt][i] = 0.f;

    for (int k0 = 0; k0 < K; k0 += 32) {
#pragma unroll
        for (int i = tid; i < 512; i += 256) {
            int r = i >> 2, qq = i & 3;
            int gr = min(row0 + r, M - 1);
            size_t go = (size_t)gr * K + k0 + qq * 8;
            *(uint4*)&sAH[r][qq * 8] = *(const uint4*)(AH + go);
            *(uint4*)&sAL[r][qq * 8] = *(const uint4*)(AL + go);
        }
        {
            int r = tid >> 2, qq = tid & 3;
            size_t go = (size_t)(col0 + r) * K + k0 + qq * 8;
            *(uint4*)&sBH[r][qq * 8] = *(const uint4*)(WH + go);
            *(uint4*)&sBL[r][qq * 8] = *(const uint4*)(WL + go);
        }
        __syncthreads();

#pragma unroll
        for (int s = 0; s < 2; s++) {
            const int ka = s * 16 + (q >> 1) * 8;
            unsigned ahi[2][4], alo[2][4];
#pragma unroll
            for (int mt = 0; mt < 2; mt++) {
                int m = wm * 32 + mt * 16 + r8 + (q & 1) * 8;
                unsigned off = (unsigned)(m * 40 + ka) * 2;
                ldsm_x4(ahi[mt], baseAH + off);
                ldsm_x4(alo[mt], baseAL + off);
            }
            const int kb = s * 16 + (l16 >> 3) * 8;
#pragma unroll
            for (int nt = 0; nt < 4; nt++) {
                int n = wn * 32 + nt * 8 + (l16 & 7);
                unsigned off = (unsigned)(n * 40 + kb) * 2;
                unsigned bhi[2], blo[2];
                ldsm_x2(bhi, baseBH + off);
                ldsm_x2(blo, baseBL + off);
#pragma unroll
                for (int mt = 0; mt < 2; mt++) {
                    mma_bf16(acc[mt][nt], ahi[mt], blo);
                    mma_bf16(acc[mt][nt], alo[mt], bhi);
                    mma_bf16(acc[mt][nt], ahi[mt], bhi);
                }
            }
        }
        __syncthreads();
    }

    const int lr = lane >> 2, lc = lane & 3;
#pragma unroll
    for (int mt = 0; mt < 2; mt++) {
#pragma unroll
        for (int nt = 0; nt < 4; nt++) {
            int r = row0 + wm * 32 + mt * 16 + lr;
            int n = col0 + wn * 32 + nt * 8 + 2 * lc;
            float b0 = bias[n], b1 = bias[n + 1];
            float v0 = acc[mt][nt][0] + b0, v1 = acc[mt][nt][1] + b1;
            float v2 = acc[mt][nt][2] + b0, v3 = acc[mt][nt][3] + b1;
            if (do_relu) {
                v0 = fmaxf(v0, 0.f); v1 = fmaxf(v1, 0.f);
                v2 = fmaxf(v2, 0.f); v3 = fmaxf(v3, 0.f);
            }
#pragma unroll
            for (int h = 0; h < 2; h++) {
                int rr = r + h * 8;
                if (rr >= M) continue;
                float e0 = h ? v2 : v0, e1 = h ? v3 : v1;
                if (mode != 2)
                    *(float2*)(C + (size_t)rr * N + n) = make_float2(e0, e1);
                if (mode >= 1) {
                    __nv_bfloat162 lo;
                    __nv_bfloat162 hi = split_pair(e0, e1, lo);
                    *(__nv_bfloat162*)(SH + (size_t)rr * N + n) = hi;
                    *(__nv_bfloat162*)(SL + (size_t)rr * N + n) = lo;
                }
            }
        }
    }
}

// ---------------- CSR build ----------------
__global__ void zero_deg_kernel() {
    int i = blockIdx.x * blockDim.x + threadIdx.x;
    if (i < Nn) g_deg[i] = 0;
}

__global__ void count_kernel(const int* __restrict__ ei) {
    int e = blockIdx.x * blockDim.x + threadIdx.x;
    if (e >= EP) return;
    int d = (e < Ee) ? ei[Ee + e] : (e - Ee);
    atomicAdd(&g_deg[d], 1);
}

__global__ __launch_bounds__(1024) void scan_kernel() {
    __shared__ int s[1024];
    int tid = threadIdx.x;
    const int chunk = (Nn + 1023) / 1024;
    int start = tid * chunk;
    int sum = 0;
    for (int i = 0; i < chunk; i++) {
        int idx = start + i;
        if (idx < Nn) sum += g_deg[idx];
    }
    s[tid] = sum;
    __syncthreads();
    for (int off = 1; off < 1024; off <<= 1) {
        int v = (tid >= off) ? s[tid - off] : 0;
        __syncthreads();
        s[tid] += v;
        __syncthreads();
    }
    int run = (tid > 0) ? s[tid - 1] : 0;
    for (int i = 0; i < chunk; i++) {
        int idx = start + i;
        if (idx < Nn) { g_rowptr[idx] = run; g_cursor[idx] = run; run += g_deg[idx]; }
    }
    if (tid == 1023) g_rowptr[Nn] = s[1023];
}

__global__ void scatter_kernel(const int* __restrict__ ei) {
    int e = blockIdx.x * blockDim.x + threadIdx.x;
    if (e >= EP) return;
    int s, d;
    if (e < Ee) { s = ei[e]; d = ei[Ee + e]; }
    else        { s = e - Ee; d = s; }
    int pos = atomicAdd(&g_cursor[d], 1);
    g_col[pos] = s;
}

// ------- GATv2 aggregation: one warp per dst node, online softmax, 4-edge unroll
__device__ __forceinline__ float lrelu(float v) { return v > 0.f ? v : 0.2f * v; }

__device__ __forceinline__ float edge_score(const float4& a, const float4& b,
                                            const float4& xr0, const float4& xr1,
                                            const float4& at0, const float4& at1) {
    float p = 0.f;
    p = fmaf(at0.x, lrelu(a.x + xr0.x), p);
    p = fmaf(at0.y, lrelu(a.y + xr0.y), p);
    p = fmaf(at0.z, lrelu(a.z + xr0.z), p);
    p = fmaf(at0.w, lrelu(a.w + xr0.w), p);
    p = fmaf(at1.x, lrelu(b.x + xr1.x), p);
    p = fmaf(at1.y, lrelu(b.y + xr1.y), p);
    p = fmaf(at1.z, lrelu(b.z + xr1.z), p);
    p = fmaf(at1.w, lrelu(b.w + xr1.w), p);
    p += __shfl_xor_sync(0xffffffffu, p, 1);
    p += __shfl_xor_sync(0xffffffffu, p, 2);
    p += __shfl_xor_sync(0xffffffffu, p, 4);
    return p;
}

__global__ __launch_bounds__(256) void gat_agg_kernel(
    const float* __restrict__ XLR,
    const float* __restrict__ att, const float* __restrict__ bias,
    float* __restrict__ OUT,
    __nv_bfloat16* __restrict__ SH, __nv_bfloat16* __restrict__ SL)
{
    int warp = (blockIdx.x * blockDim.x + threadIdx.x) >> 5;
    if (warp >= Nn) return;
    int lane = threadIdx.x & 31;

    const float4* xr4 = reinterpret_cast<const float4*>(XLR + (size_t)warp * 512 + 256 + lane * 8);
    float4 xr0 = xr4[0], xr1 = xr4[1];
    const float4* at4 = reinterpret_cast<const float4*>(att + lane * 8);
    float4 at0 = at4[0], at1 = at4[1];

    int s0 = g_rowptr[warp], s1 = g_rowptr[warp + 1];

    float m = -3.0e38f, denom = 0.f;
    float acc[8] = {0.f, 0.f, 0.f, 0.f, 0.f, 0.f, 0.f, 0.f};

    int slot = s0;
    for (; slot + 4 <= s1; slot += 4) {
        int src0 = g_col[slot],     src1 = g_col[slot + 1];
        int src2 = g_col[slot + 2], src3 = g_col[slot + 3];
        const float4* x0 = reinterpret_cast<const float4*>(XLR + (size_t)src0 * 512 + lane * 8);
        const float4* x1 = reinterpret_cast<const float4*>(XLR + (size_t)src1 * 512 + lane * 8);
        const float4* x2 = reinterpret_cast<const float4*>(XLR + (size_t)src2 * 512 + lane * 8);
        const float4* x3 = reinterpret_cast<const float4*>(XLR + (size_t)src3 * 512 + lane * 8);
        float4 a0 = x0[0], b0 = x0[1];
        float4 a1 = x1[0], b1 = x1[1];
        float4 a2 = x2[0], b2 = x2[1];
        float4 a3 = x3[0], b3 = x3[1];

        float p0 = edge_score(a0, b0, xr0, xr1, at0, at1);
        float p1 = edge_score(a1, b1, xr0, xr1, at0, at1);
        float p2 = edge_score(a2, b2, xr0, xr1, at0, at1);
        float p3 = edge_score(a3, b3, xr0, xr1, at0, at1);

        float mnew = fmaxf(fmaxf(m, fmaxf(p0, p1)), fmaxf(p2, p3));
        float sc = __expf(m - mnew);
        float e0 = __expf(p0 - mnew);
        float e1 = __expf(p1 - mnew);
        float e2 = __expf(p2 - mnew);
        float e3 = __expf(p3 - mnew);
        m = mnew;
        denom = denom * sc + e0 + e1 + e2 + e3;
        acc[0] = fmaf(e3, a3.x, fmaf(e2, a2.x, fmaf(e1, a1.x, fmaf(e0, a0.x, acc[0] * sc))));
        acc[1] = fmaf(e3, a3.y, fmaf(e2, a2.y, fmaf(e1, a1.y, fmaf(e0, a0.y, acc[1] * sc))));
        acc[2] = fmaf(e3, a3.z, fmaf(e2, a2.z, fmaf(e1, a1.z, fmaf(e0, a0.z, acc[2] * sc))));
        acc[3] = fmaf(e3, a3.w, fmaf(e2, a2.w, fmaf(e1, a1.w, fmaf(e0, a0.w, acc[3] * sc))));
        acc[4] = fmaf(e3, b3.x, fmaf(e2, b2.x, fmaf(e1, b1.x, fmaf(e0, b0.x, acc[4] * sc))));
        acc[5] = fmaf(e3, b3.y, fmaf(e2, b2.y, fmaf(e1, b1.y, fmaf(e0, b0.y, acc[5] * sc))));
        acc[6] = fmaf(e3, b3.z, fmaf(e2, b2.z, fmaf(e1, b1.z, fmaf(e0, b0.z, acc[6] * sc))));
        acc[7] = fmaf(e3, b3.w, fmaf(e2, b2.w, fmaf(e1, b1.w, fmaf(e0, b0.w, acc[7] * sc))));
    }
    for (; slot < s1; slot++) {
        int src = g_col[slot];
        const float4* x0 = reinterpret_cast<const float4*>(XLR + (size_t)src * 512 + lane * 8);
        float4 a = x0[0], b = x0[1];
        float p = edge_score(a, b, xr0, xr1, at0, at1);
        float mnew = fmaxf(m, p);
        float sc = __expf(m - mnew);
        float ex = __expf(p - mnew);
        m = mnew;
        denom = denom * sc + ex;
        acc[0] = fmaf(ex, a.x, acc[0] * sc);
        acc[1] = fmaf(ex, a.y, acc[1] * sc);
        acc[2] = fmaf(ex, a.z, acc[2] * sc);
        acc[3] = fmaf(ex, a.w, acc[3] * sc);
        acc[4] = fmaf(ex, b.x, acc[4] * sc);
        acc[5] = fmaf(ex, b.y, acc[5] * sc);
        acc[6] = fmaf(ex, b.z, acc[6] * sc);
        acc[7] = fmaf(ex, b.w, acc[7] * sc);
    }

    float inv = 1.0f / (denom + 1e-16f);
    const float4* bi4 = reinterpret_cast<const float4*>(bias + lane * 8);
    float4 bb0 = bi4[0], bb1 = bi4[1];
    float o[8];
    o[0] = fmaxf(acc[0] * inv + bb0.x, 0.f);
    o[1] = fmaxf(acc[1] * inv + bb0.y, 0.f);
    o[2] = fmaxf(acc[2] * inv + bb0.z, 0.f);
    o[3] = fmaxf(acc[3] * inv + bb0.w, 0.f);
    o[4] = fmaxf(acc[4] * inv + bb1.x, 0.f);
    o[5] = fmaxf(acc[5] * inv + bb1.y, 0.f);
    o[6] = fmaxf(acc[6] * inv + bb1.z, 0.f);
    o[7] = fmaxf(acc[7] * inv + bb1.w, 0.f);

    float4* out4 = reinterpret_cast<float4*>(OUT + (size_t)warp * 256 + lane * 8);
    out4[0] = make_float4(o[0], o[1], o[2], o[3]);
    out4[1] = make_float4(o[4], o[5], o[6], o[7]);

    if (SH) {
        size_t base = (size_t)warp * 256 + lane * 8;
#pragma unroll
        for (int j = 0; j < 4; j++) {
            __nv_bfloat162 lo;
            __nv_bfloat162 hi = split_pair(o[2 * j], o[2 * j + 1], lo);
            *(__nv_bfloat162*)(SH + base + 2 * j) = hi;
            *(__nv_bfloat162*)(SL + base + 2 * j) = lo;
        }
    }
}

// ---------------- dueling head (gather fused) ---------------------------------
__global__ __launch_bounds__(128) void duel_kernel(
    const int* __restrict__ indices,
    const float* __restrict__ qw1, const float* __restrict__ qb1,
    const float* __restrict__ qw2, const float* __restrict__ qb2,
    const float* __restrict__ vw1, const float* __restrict__ vb1,
    const float* __restrict__ vw2, const float* __restrict__ vb2,
    float* __restrict__ out)
{
    int b = blockIdx.x;
    int t = threadIdx.x;
    int node = indices[b];
    __shared__ float f[CAT];
    __shared__ float r0[128], r1[128], rv[128];
    for (int i = t; i < CAT; i += 128) {
        float v;
        if (i < 64)       v = g_H [node * 64 + i];
        else if (i < 320) v = g_C1[node * 256 + (i - 64)];
        else              v = g_C2[node * 256 + (i - 320)];
        f[i] = v;
    }
    __syncthreads();

    float sq = qb1[t], sv = vb1[t];
    for (int j = 0; j < CAT; j++) {
        float fv = f[j];
        sq = fmaf(fv, qw1[j * 128 + t], sq);
        sv = fmaf(fv, vw1[j * 128 + t], sv);
    }
    sq = fmaxf(sq, 0.f);
    sv = fmaxf(sv, 0.f);
    r0[t] = sq * qw2[t * 2 + 0];
    r1[t] = sq * qw2[t * 2 + 1];
    rv[t] = sv * vw2[t];
    __syncthreads();
    for (int off = 64; off > 0; off >>= 1) {
        if (t < off) {
            r0[t] += r0[t + off];
            r1[t] += r1[t + off];
            rv[t] += rv[t + off];
        }
        __syncthreads();
    }
    if (t == 0) {
        float q0 = r0[0] + qb2[0];
        float q1 = r1[0] + qb2[1];
        float v  = rv[0] + vb2[0];
        float mth = 0.5f * (q0 + q1);
        out[b * 2 + 0] = q0 - mth + v;
        out[b * 2 + 1] = q1 - mth + v;
    }
}

// ---------------- host ----------------
extern "C" void kernel_launch(void* const* d_in, const int* in_sizes, int n_in,
                              void* d_out, int out_size)
{
    const float* x       = (const float*)d_in[0];
    const int*   ei      = (const int*)  d_in[1];
    const int*   indices = (const int*)  d_in[2];
    const float* enc_w1 = (const float*)d_in[3],  *enc_b1 = (const float*)d_in[4];
    const float* enc_w2 = (const float*)d_in[5],  *enc_b2 = (const float*)d_in[6];
    const float* wl1 = (const float*)d_in[7],  *bl1 = (const float*)d_in[8];
    const float* wr1 = (const float*)d_in[9],  *br1 = (const float*)d_in[10];
    const float* att1 = (const float*)d_in[11], *bias1 = (const float*)d_in[12];
    const float* wl2 = (const float*)d_in[13], *bl2 = (const float*)d_in[14];
    const float* wr2 = (const float*)d_in[15], *br2 = (const float*)d_in[16];
    const float* att2 = (const float*)d_in[17], *bias2 = (const float*)d_in[18];
    const float* qw1 = (const float*)d_in[19], *qb1 = (const float*)d_in[20];
    const float* qw2 = (const float*)d_in[21], *qb2 = (const float*)d_in[22];
    const float* vw1 = (const float*)d_in[23], *vb1 = (const float*)d_in[24];
    const float* vw2 = (const float*)d_in[25], *vb2 = (const float*)d_in[26];

    float *pH, *pXLR, *pC1, *pC2, *pB1, *pB2;
    __nv_bfloat16 *pA1H, *pA1L, *pA2H, *pA2L, *pWH, *pWL;
    cudaGetSymbolAddress((void**)&pH,   g_H);
    cudaGetSymbolAddress((void**)&pXLR, g_XLR);
    cudaGetSymbolAddress((void**)&pC1,  g_C1);
    cudaGetSymbolAddress((void**)&pC2,  g_C2);
    cudaGetSymbolAddress((void**)&pB1,  g_biascat1);
    cudaGetSymbolAddress((void**)&pB2,  g_biascat2);
    cudaGetSymbolAddress((void**)&pA1H, g_A1H);
    cudaGetSymbolAddress((void**)&pA1L, g_A1L);
    cudaGetSymbolAddress((void**)&pA2H, g_A2H);
    cudaGetSymbolAddress((void**)&pA2L, g_A2L);
    cudaGetSymbolAddress((void**)&pWH,  g_WT_hi);
    cudaGetSymbolAddress((void**)&pWL,  g_WT_lo);

    // side stream + events (created once; no device memory)
    static cudaStream_t s_csr = nullptr;
    static cudaEvent_t evFork = nullptr, evJoin = nullptr, evPrep = nullptr;
    if (!s_csr) {
        cudaStreamCreateWithFlags(&s_csr, cudaStreamNonBlocking);
        cudaEventCreateWithFlags(&evFork, cudaEventDisableTiming);
        cudaEventCreateWithFlags(&evJoin, cudaEventDisableTiming);
        cudaEventCreateWithFlags(&evPrep, cudaEventDisableTiming);
    }

    const int MB = (Nn + 127) / 128;   // 157 row-blocks

    // fork: weight prep + CSR chain on side stream; split_A on main
    cudaEventRecord(evFork, 0);
    cudaStreamWaitEvent(s_csr, evFork, 0);

    prep_weights_kernel<<<(WT_TOTAL + 1024 + 255) / 256, 256, 0, s_csr>>>(
        enc_w1, enc_w2, wl1, wr1, wl2, wr2, bl1, br1, bl2, br2);
    cudaEventRecord(evPrep, s_csr);
    zero_deg_kernel<<<(Nn + 255) / 256, 256, 0, s_csr>>>();
    count_kernel<<<(EP + 255) / 256, 256, 0, s_csr>>>(ei);
    scan_kernel<<<1, 1024, 0, s_csr>>>();
    scatter_kernel<<<(EP + 255) / 256, 256, 0, s_csr>>>(ei);
    cudaEventRecord(evJoin, s_csr);

    // main: input split (independent of weights)
    split_A_kernel<<<(Nn * 64 / 4 + 255) / 256, 256>>>(x, pA1H, pA1L, Nn * 64 / 4);

    // enc1 needs split_A (main) + prep (side)
    cudaStreamWaitEvent(0, evPrep, 0);
    gemm_bf16_ldsm<<<dim3(8, MB), 256>>>(pA1H, pA1L, pWH, pWL, enc_b1,
                                         nullptr, pA2H, pA2L, Nn, 512, 64, 2, 1);
    gemm_bf16_ldsm<<<dim3(1, MB), 256>>>(pA2H, pA2L, pWH + 32768, pWL + 32768, enc_b2,
                                         pH, pA1H, pA1L, Nn, 64, 512, 1, 1);
    gemm_bf16_ldsm<<<dim3(8, MB), 256>>>(pA1H, pA1L, pWH + 65536, pWL + 65536, pB1,
                                         pXLR, nullptr, nullptr, Nn, 512, 64, 0, 0);

    // join: agg needs both conv1 (main) and CSR (side)
    cudaStreamWaitEvent(0, evJoin, 0);
    gat_agg_kernel<<<Nn / 8, 256>>>(pXLR, att1, bias1, pC1, pA2H, pA2L);

    gemm_bf16_ldsm<<<dim3(8, MB), 256>>>(pA2H, pA2L, pWH + 98304, pWL + 98304, pB2,
                                         pXLR, nullptr, nullptr, Nn, 512, 256, 0, 0);
    gat_agg_kernel<<<Nn / 8, 256>>>(pXLR, att2, bias2, pC2, nullptr, nullptr);

    duel_kernel<<<Bb, 128>>>(indices, qw1, qb1, qw2, qb2, vw1, vb1, vw2, vb2,
                             (float*)d_out);
}